// round 1
// baseline (speedup 1.0000x reference)
#include <cuda_runtime.h>
#include <math.h>

#define NN 100000
#define EE 1600000
#define HH 128
#define BN_EPS 1e-5f

// ---------------- device scratch (no allocations allowed) ----------------
__device__ __align__(16) float g_H[NN * HH];     // current hidden state
__device__ __align__(16) float g_Z[NN * HH];     // pre-BN GEMM output
__device__ __align__(16) float g_AGG[NN * HH];   // SpMM output
__device__ __align__(16) float g_deg[NN];        // in-degree (as float)
__device__ __align__(16) float g_val[EE];        // normalized edge values
__device__ __align__(16) float g_sum[HH];
__device__ __align__(16) float g_sumsq[HH];

// ---------------- small utility kernels ----------------
__global__ void zero_f4(float4* p, int n4) {
    int i = blockIdx.x * blockDim.x + threadIdx.x;
    int stride = gridDim.x * blockDim.x;
    float4 z = make_float4(0.f, 0.f, 0.f, 0.f);
    for (; i < n4; i += stride) p[i] = z;
}

__global__ void zero_stats_kernel() {
    int i = threadIdx.x;
    if (i < HH) { g_sum[i] = 0.f; g_sumsq[i] = 0.f; }
}

__global__ void degree_kernel(const int* __restrict__ col) {
    int e = blockIdx.x * blockDim.x + threadIdx.x;
    if (e < EE) atomicAdd(&g_deg[col[e]], 1.0f);
}

__global__ void val_kernel(const int* __restrict__ row, const int* __restrict__ col,
                           const float* __restrict__ w) {
    int e = blockIdx.x * blockDim.x + threadIdx.x;
    if (e < EE) {
        float v = w[e] * rsqrtf(g_deg[col[e]]) * rsqrtf(g_deg[row[e]]);
        if (!isfinite(v)) v = 0.f;   // nan_to_num (inf -> 0)
        g_val[e] = v;
    }
}

// ---------------- SpMM: out[col] += val * h[row], one warp per edge ----------------
__global__ void spmm_kernel(const int* __restrict__ row, const int* __restrict__ col) {
    int gtid   = blockIdx.x * blockDim.x + threadIdx.x;
    int warp   = gtid >> 5;
    int lane   = threadIdx.x & 31;
    int nwarps = (gridDim.x * blockDim.x) >> 5;
    const float4* src4 = reinterpret_cast<const float4*>(g_H);
    for (int e = warp; e < EE; e += nwarps) {
        float v = g_val[e];
        if (v == 0.f) continue;
        int r = row[e], c = col[e];
        float4 hv = src4[r * 32 + lane];               // coalesced 512B gather (L2-resident)
        float* dst = &g_AGG[c * HH + lane * 4];
        asm volatile("red.global.add.v4.f32 [%0], {%1,%2,%3,%4};"
                     :: "l"(dst), "f"(v * hv.x), "f"(v * hv.y),
                        "f"(v * hv.z), "f"(v * hv.w)
                     : "memory");
    }
}

// ---------------- dense GEMM: C[M,128] = A[M,128] @ B[128,128] + bias ----------------
// BM=128, BN=128, BK=8, 256 threads, 8x8 per-thread tile.
__global__ __launch_bounds__(256) void gemm_bias_kernel(
    const float* __restrict__ A, const float* __restrict__ B,
    const float* __restrict__ bias, float* __restrict__ C, int M)
{
    __shared__ float As[8][128];   // [k][m]
    __shared__ float Bs[8][128];   // [k][n]

    const int tid = threadIdx.x;
    const int block_row = blockIdx.x * 128;
    const int trow = tid / 16;          // 0..15
    const int tcol = tid % 16;          // 0..15

    const int a_row = tid >> 1;         // 0..127
    const int a_kc  = (tid & 1) * 4;    // 0 or 4
    const int b_row = tid >> 5;         // 0..7
    const int b_col = (tid & 31) * 4;   // 0..124

    float acc[8][8];
    #pragma unroll
    for (int i = 0; i < 8; i++)
        #pragma unroll
        for (int j = 0; j < 8; j++) acc[i][j] = 0.f;

    for (int k0 = 0; k0 < 128; k0 += 8) {
        int gr = block_row + a_row;
        float4 av = (gr < M)
            ? *reinterpret_cast<const float4*>(&A[(size_t)gr * 128 + k0 + a_kc])
            : make_float4(0.f, 0.f, 0.f, 0.f);
        As[a_kc + 0][a_row] = av.x;
        As[a_kc + 1][a_row] = av.y;
        As[a_kc + 2][a_row] = av.z;
        As[a_kc + 3][a_row] = av.w;

        *reinterpret_cast<float4*>(&Bs[b_row][b_col]) =
            *reinterpret_cast<const float4*>(&B[(k0 + b_row) * 128 + b_col]);

        __syncthreads();

        #pragma unroll
        for (int kk = 0; kk < 8; kk++) {
            float ra[8], rb[8];
            *reinterpret_cast<float4*>(&ra[0]) = *reinterpret_cast<const float4*>(&As[kk][trow * 8 + 0]);
            *reinterpret_cast<float4*>(&ra[4]) = *reinterpret_cast<const float4*>(&As[kk][trow * 8 + 4]);
            *reinterpret_cast<float4*>(&rb[0]) = *reinterpret_cast<const float4*>(&Bs[kk][tcol * 8 + 0]);
            *reinterpret_cast<float4*>(&rb[4]) = *reinterpret_cast<const float4*>(&Bs[kk][tcol * 8 + 4]);
            #pragma unroll
            for (int i = 0; i < 8; i++)
                #pragma unroll
                for (int j = 0; j < 8; j++)
                    acc[i][j] += ra[i] * rb[j];
        }
        __syncthreads();
    }

    float bv[8];
    #pragma unroll
    for (int j = 0; j < 8; j++) bv[j] = bias[tcol * 8 + j];

    #pragma unroll
    for (int i = 0; i < 8; i++) {
        int r = block_row + trow * 8 + i;
        if (r < M) {
            float o[8];
            #pragma unroll
            for (int j = 0; j < 8; j++) o[j] = acc[i][j] + bv[j];
            *reinterpret_cast<float4*>(&C[(size_t)r * 128 + tcol * 8 + 0]) =
                *reinterpret_cast<const float4*>(&o[0]);
            *reinterpret_cast<float4*>(&C[(size_t)r * 128 + tcol * 8 + 4]) =
                *reinterpret_cast<const float4*>(&o[4]);
        }
    }
}

// ---------------- BatchNorm stats: per-column sum / sumsq ----------------
__global__ void bn_stats_kernel(const float* __restrict__ z) {
    int c = threadIdx.x;                 // 0..127, one column per thread
    float s = 0.f, ss = 0.f;
    for (int r = blockIdx.x; r < NN; r += gridDim.x) {
        float v = z[(size_t)r * 128 + c];
        s  += v;
        ss += v * v;
    }
    atomicAdd(&g_sum[c], s);
    atomicAdd(&g_sumsq[c], ss);
}

// ---------------- BN apply + ReLU (+ optional residual) ----------------
__global__ void bn_apply_kernel(const float* __restrict__ z,
                                const float* __restrict__ gamma,
                                const float* __restrict__ beta,
                                const float* __restrict__ res,  // may be null
                                float* __restrict__ out)
{
    const float inv_n = 1.0f / (float)NN;
    int i = blockIdx.x * blockDim.x + threadIdx.x;
    int stride = gridDim.x * blockDim.x;
    const int n4 = NN * (HH / 4);
    for (; i < n4; i += stride) {
        int c0 = (i & 31) * 4;           // column of first component
        float4 zv = reinterpret_cast<const float4*>(z)[i];
        float o[4] = {zv.x, zv.y, zv.z, zv.w};
        #pragma unroll
        for (int j = 0; j < 4; j++) {
            int c = c0 + j;
            float m  = g_sum[c] * inv_n;
            float vr = g_sumsq[c] * inv_n - m * m;
            float rs = rsqrtf(vr + BN_EPS);
            float y = (o[j] - m) * rs * gamma[c] + beta[c];
            o[j] = fmaxf(y, 0.f);
        }
        float4 ov = make_float4(o[0], o[1], o[2], o[3]);
        if (res != nullptr) {
            float4 rv = reinterpret_cast<const float4*>(res)[i];
            ov.x += rv.x; ov.y += rv.y; ov.z += rv.z; ov.w += rv.w;
        }
        reinterpret_cast<float4*>(out)[i] = ov;
    }
}

// ---------------- launch ----------------
extern "C" void kernel_launch(void* const* d_in, const int* in_sizes, int n_in,
                              void* d_out, int out_size)
{
    const float* x      = (const float*)d_in[0];
    const int*   ei     = (const int*)  d_in[1];
    const float* ew     = (const float*)d_in[2];
    const float* fc_w   = (const float*)d_in[3];
    const float* fc_b   = (const float*)d_in[4];
    const float* conv_w = (const float*)d_in[5];
    const float* conv_b = (const float*)d_in[6];
    const float* gamma  = (const float*)d_in[7];
    const float* beta   = (const float*)d_in[8];
    float* out = (float*)d_out;

    const int* row = ei;
    const int* col = ei + EE;

    void *pH, *pZ, *pAGG, *pDeg;
    cudaGetSymbolAddress(&pH, g_H);
    cudaGetSymbolAddress(&pZ, g_Z);
    cudaGetSymbolAddress(&pAGG, g_AGG);
    cudaGetSymbolAddress(&pDeg, g_deg);
    float* H   = (float*)pH;
    float* Z   = (float*)pZ;
    float* AGG = (float*)pAGG;

    const int egrid = (EE + 255) / 256;
    const int ggrid = (NN + 127) / 128;

    // degree + normalized edge values (shared by both layers)
    zero_f4<<<128, 256>>>((float4*)pDeg, NN / 4);
    degree_kernel<<<egrid, 256>>>(col);
    val_kernel<<<egrid, 256>>>(row, col, ew);

    // input projection + BN + ReLU
    gemm_bias_kernel<<<ggrid, 256>>>(x, fc_w, fc_b, Z, NN);
    zero_stats_kernel<<<1, 128>>>();
    bn_stats_kernel<<<512, 128>>>(Z);
    bn_apply_kernel<<<4096, 256>>>(Z, gamma, beta, nullptr, H);

    for (int l = 0; l < 2; l++) {
        zero_f4<<<4096, 256>>>((float4*)pAGG, NN * HH / 4);
        spmm_kernel<<<2048, 256>>>(row, col);
        gemm_bias_kernel<<<ggrid, 256>>>(AGG, conv_w + l * HH * HH, conv_b + l * HH, Z, NN);
        zero_stats_kernel<<<1, 128>>>();
        bn_stats_kernel<<<512, 128>>>(Z);
        bn_apply_kernel<<<4096, 256>>>(Z, gamma + (l + 1) * HH, beta + (l + 1) * HH,
                                       H, (l == 1) ? out : H);
    }
}

// round 2
// speedup vs baseline: 1.6819x; 1.6819x over previous
#include <cuda_runtime.h>
#include <math.h>

#define NN 100000
#define EE 1600000
#define HH 128
#define BN_EPS 1e-5f
#define CHUNK 512
#define NCHUNK ((NN + CHUNK - 1) / CHUNK)   // 196

// ---------------- device scratch (no allocations allowed) ----------------
__device__ __align__(16) float g_H[NN * HH];     // current hidden state
__device__ __align__(16) float g_Z[NN * HH];     // pre-BN GEMM output
__device__ __align__(16) float g_AGG[NN * HH];   // SpMM output
__device__ __align__(16) int   g_degi[NN];       // in-degree (int)
__device__ __align__(16) int   g_off[NN + 1];    // CSR offsets (by destination)
__device__ __align__(16) int   g_cur[NN];        // scatter cursors
__device__ __align__(16) int   g_src[EE];        // CSR: source node per slot
__device__ __align__(16) float g_ev[EE];         // CSR: normalized edge value per slot
__device__ __align__(16) int   g_csum[NCHUNK];   // chunk sums for scan
__device__ __align__(16) float g_sum[HH];
__device__ __align__(16) float g_sumsq[HH];

// ---------------- utility kernels ----------------
__global__ void zero_int(int* p, int n) {
    int i = blockIdx.x * blockDim.x + threadIdx.x;
    int stride = gridDim.x * blockDim.x;
    for (; i < n; i += stride) p[i] = 0;
}

__global__ void zero_stats_kernel() {
    int i = threadIdx.x;
    if (i < HH) { g_sum[i] = 0.f; g_sumsq[i] = 0.f; }
}

__global__ void degree_kernel(const int* __restrict__ col) {
    int e = blockIdx.x * blockDim.x + threadIdx.x;
    if (e < EE) atomicAdd(&g_degi[col[e]], 1);
}

// ---------------- CSR build: two-level exclusive scan ----------------
__global__ void chunk_sums_kernel() {
    __shared__ int sh[CHUNK];
    int t = threadIdx.x;
    int n = blockIdx.x * CHUNK + t;
    sh[t] = (n < NN) ? g_degi[n] : 0;
    __syncthreads();
    for (int s = CHUNK / 2; s > 0; s >>= 1) {
        if (t < s) sh[t] += sh[t + s];
        __syncthreads();
    }
    if (t == 0) g_csum[blockIdx.x] = sh[0];
}

__global__ void scan_csum_kernel() {
    if (threadIdx.x == 0) {
        int acc = 0;
        for (int i = 0; i < NCHUNK; i++) {
            int t = g_csum[i];
            g_csum[i] = acc;
            acc += t;
        }
    }
}

__global__ void scan_offsets_kernel() {
    __shared__ int sh[CHUNK];
    int t = threadIdx.x;
    int n = blockIdx.x * CHUNK + t;
    int v = (n < NN) ? g_degi[n] : 0;
    sh[t] = v;
    __syncthreads();
    // inclusive Hillis-Steele
    for (int s = 1; s < CHUNK; s <<= 1) {
        int add = (t >= s) ? sh[t - s] : 0;
        __syncthreads();
        sh[t] += add;
        __syncthreads();
    }
    int excl = sh[t] - v + g_csum[blockIdx.x];
    if (n < NN) { g_off[n] = excl; g_cur[n] = excl; }
    if (n == NN - 1) g_off[NN] = excl + v;   // == EE
}

// ---------------- edge normalization + scatter into CSR ----------------
__global__ void val_scatter_kernel(const int* __restrict__ row, const int* __restrict__ col,
                                   const float* __restrict__ w) {
    int e = blockIdx.x * blockDim.x + threadIdx.x;
    if (e < EE) {
        int r = row[e], c = col[e];
        float v = w[e] * rsqrtf((float)g_degi[c]) * rsqrtf((float)g_degi[r]);
        if (!isfinite(v)) v = 0.f;   // nan_to_num (inf -> 0, deg 0 -> rsqrt(0)=inf)
        int p = atomicAdd(&g_cur[c], 1);
        g_src[p] = r;
        g_ev[p]  = v;
    }
}

// ---------------- SpMM (CSR by destination): one warp per node, no atomics ----------------
__global__ __launch_bounds__(256) void spmm_csr_kernel() {
    int warp = (blockIdx.x * blockDim.x + threadIdx.x) >> 5;
    int lane = threadIdx.x & 31;
    if (warp >= NN) return;
    int s = g_off[warp];
    int e = g_off[warp + 1];
    const float4* H4 = reinterpret_cast<const float4*>(g_H);
    float4 acc = make_float4(0.f, 0.f, 0.f, 0.f);
    int k = s;
    for (; k + 1 < e; k += 2) {
        int   s0 = g_src[k],   s1 = g_src[k + 1];
        float v0 = g_ev[k],    v1 = g_ev[k + 1];
        float4 a = H4[(size_t)s0 * 32 + lane];
        float4 b = H4[(size_t)s1 * 32 + lane];
        acc.x += v0 * a.x + v1 * b.x;
        acc.y += v0 * a.y + v1 * b.y;
        acc.z += v0 * a.z + v1 * b.z;
        acc.w += v0 * a.w + v1 * b.w;
    }
    if (k < e) {
        int   s0 = g_src[k];
        float v0 = g_ev[k];
        float4 a = H4[(size_t)s0 * 32 + lane];
        acc.x += v0 * a.x; acc.y += v0 * a.y;
        acc.z += v0 * a.z; acc.w += v0 * a.w;
    }
    reinterpret_cast<float4*>(g_AGG)[(size_t)warp * 32 + lane] = acc;
}

// ---------------- dense GEMM: C[M,128] = A[M,128] @ B[128,128] + bias ----------------
// BM=128, BN=128, BK=8, 256 threads, 8x8 per-thread tile.
// Fused BN-stats epilogue: accumulates per-column sum / sumsq into g_sum/g_sumsq.
__global__ __launch_bounds__(256) void gemm_bias_stats_kernel(
    const float* __restrict__ A, const float* __restrict__ B,
    const float* __restrict__ bias, float* __restrict__ C, int M)
{
    __shared__ float As[8][128];   // [k][m]
    __shared__ float Bs[8][128];   // [k][n]
    __shared__ float s_sum[128];
    __shared__ float s_ssq[128];

    const int tid = threadIdx.x;
    const int block_row = blockIdx.x * 128;
    const int trow = tid / 16;          // 0..15
    const int tcol = tid % 16;          // 0..15

    const int a_row = tid >> 1;         // 0..127
    const int a_kc  = (tid & 1) * 4;    // 0 or 4
    const int b_row = tid >> 5;         // 0..7
    const int b_col = (tid & 31) * 4;   // 0..124

    if (tid < 128) { s_sum[tid] = 0.f; s_ssq[tid] = 0.f; }

    float acc[8][8];
    #pragma unroll
    for (int i = 0; i < 8; i++)
        #pragma unroll
        for (int j = 0; j < 8; j++) acc[i][j] = 0.f;

    for (int k0 = 0; k0 < 128; k0 += 8) {
        int gr = block_row + a_row;
        float4 av = (gr < M)
            ? *reinterpret_cast<const float4*>(&A[(size_t)gr * 128 + k0 + a_kc])
            : make_float4(0.f, 0.f, 0.f, 0.f);
        As[a_kc + 0][a_row] = av.x;
        As[a_kc + 1][a_row] = av.y;
        As[a_kc + 2][a_row] = av.z;
        As[a_kc + 3][a_row] = av.w;

        *reinterpret_cast<float4*>(&Bs[b_row][b_col]) =
            *reinterpret_cast<const float4*>(&B[(k0 + b_row) * 128 + b_col]);

        __syncthreads();

        #pragma unroll
        for (int kk = 0; kk < 8; kk++) {
            float ra[8], rb[8];
            *reinterpret_cast<float4*>(&ra[0]) = *reinterpret_cast<const float4*>(&As[kk][trow * 8 + 0]);
            *reinterpret_cast<float4*>(&ra[4]) = *reinterpret_cast<const float4*>(&As[kk][trow * 8 + 4]);
            *reinterpret_cast<float4*>(&rb[0]) = *reinterpret_cast<const float4*>(&Bs[kk][tcol * 8 + 0]);
            *reinterpret_cast<float4*>(&rb[4]) = *reinterpret_cast<const float4*>(&Bs[kk][tcol * 8 + 4]);
            #pragma unroll
            for (int i = 0; i < 8; i++)
                #pragma unroll
                for (int j = 0; j < 8; j++)
                    acc[i][j] += ra[i] * rb[j];
        }
        __syncthreads();
    }

    float bv[8];
    #pragma unroll
    for (int j = 0; j < 8; j++) bv[j] = bias[tcol * 8 + j];

    float ls[8], lss[8];
    #pragma unroll
    for (int j = 0; j < 8; j++) { ls[j] = 0.f; lss[j] = 0.f; }

    #pragma unroll
    for (int i = 0; i < 8; i++) {
        int r = block_row + trow * 8 + i;
        if (r < M) {
            float o[8];
            #pragma unroll
            for (int j = 0; j < 8; j++) {
                o[j] = acc[i][j] + bv[j];
                ls[j]  += o[j];
                lss[j] += o[j] * o[j];
            }
            *reinterpret_cast<float4*>(&C[(size_t)r * 128 + tcol * 8 + 0]) =
                *reinterpret_cast<const float4*>(&o[0]);
            *reinterpret_cast<float4*>(&C[(size_t)r * 128 + tcol * 8 + 4]) =
                *reinterpret_cast<const float4*>(&o[4]);
        }
    }

    #pragma unroll
    for (int j = 0; j < 8; j++) {
        atomicAdd(&s_sum[tcol * 8 + j], ls[j]);
        atomicAdd(&s_ssq[tcol * 8 + j], lss[j]);
    }
    __syncthreads();
    if (tid < 128) {
        atomicAdd(&g_sum[tid],   s_sum[tid]);
        atomicAdd(&g_sumsq[tid], s_ssq[tid]);
    }
}

// ---------------- BN apply + ReLU (+ optional residual) ----------------
__global__ void bn_apply_kernel(const float* __restrict__ z,
                                const float* __restrict__ gamma,
                                const float* __restrict__ beta,
                                const float* __restrict__ res,  // may be null
                                float* __restrict__ out)
{
    const float inv_n = 1.0f / (float)NN;
    int i = blockIdx.x * blockDim.x + threadIdx.x;
    int stride = gridDim.x * blockDim.x;
    const int n4 = NN * (HH / 4);
    for (; i < n4; i += stride) {
        int c0 = (i & 31) * 4;
        float4 zv = reinterpret_cast<const float4*>(z)[i];
        float o[4] = {zv.x, zv.y, zv.z, zv.w};
        #pragma unroll
        for (int j = 0; j < 4; j++) {
            int c = c0 + j;
            float m  = g_sum[c] * inv_n;
            float vr = g_sumsq[c] * inv_n - m * m;
            float rs = rsqrtf(vr + BN_EPS);
            float y = (o[j] - m) * rs * gamma[c] + beta[c];
            o[j] = fmaxf(y, 0.f);
        }
        float4 ov = make_float4(o[0], o[1], o[2], o[3]);
        if (res != nullptr) {
            float4 rv = reinterpret_cast<const float4*>(res)[i];
            ov.x += rv.x; ov.y += rv.y; ov.z += rv.z; ov.w += rv.w;
        }
        reinterpret_cast<float4*>(out)[i] = ov;
    }
}

// ---------------- launch ----------------
extern "C" void kernel_launch(void* const* d_in, const int* in_sizes, int n_in,
                              void* d_out, int out_size)
{
    const float* x      = (const float*)d_in[0];
    const int*   ei     = (const int*)  d_in[1];
    const float* ew     = (const float*)d_in[2];
    const float* fc_w   = (const float*)d_in[3];
    const float* fc_b   = (const float*)d_in[4];
    const float* conv_w = (const float*)d_in[5];
    const float* conv_b = (const float*)d_in[6];
    const float* gamma  = (const float*)d_in[7];
    const float* beta   = (const float*)d_in[8];
    float* out = (float*)d_out;

    const int* row = ei;
    const int* col = ei + EE;

    void *pH, *pZ, *pAGG, *pDegi;
    cudaGetSymbolAddress(&pH, g_H);
    cudaGetSymbolAddress(&pZ, g_Z);
    cudaGetSymbolAddress(&pAGG, g_AGG);
    cudaGetSymbolAddress(&pDegi, g_degi);
    float* H   = (float*)pH;
    float* Z   = (float*)pZ;
    float* AGG = (float*)pAGG;

    const int egrid = (EE + 255) / 256;
    const int ggrid = (NN + 127) / 128;

    // ---- CSR build (shared by both layers) ----
    zero_int<<<128, 256>>>((int*)pDegi, NN);
    degree_kernel<<<egrid, 256>>>(col);
    chunk_sums_kernel<<<NCHUNK, CHUNK>>>();
    scan_csum_kernel<<<1, 32>>>();
    scan_offsets_kernel<<<NCHUNK, CHUNK>>>();
    val_scatter_kernel<<<egrid, 256>>>(row, col, ew);

    // ---- input projection + BN + ReLU ----
    zero_stats_kernel<<<1, 128>>>();
    gemm_bias_stats_kernel<<<ggrid, 256>>>(x, fc_w, fc_b, Z, NN);
    bn_apply_kernel<<<4096, 256>>>(Z, gamma, beta, nullptr, H);

    for (int l = 0; l < 2; l++) {
        spmm_csr_kernel<<<(NN * 32 + 255) / 256, 256>>>();
        zero_stats_kernel<<<1, 128>>>();
        gemm_bias_stats_kernel<<<ggrid, 256>>>(AGG, conv_w + l * HH * HH, conv_b + l * HH, Z, NN);
        bn_apply_kernel<<<4096, 256>>>(Z, gamma + (l + 1) * HH, beta + (l + 1) * HH,
                                       H, (l == 1) ? out : H);
    }
}

// round 4
// speedup vs baseline: 1.8474x; 1.0984x over previous
#include <cuda_runtime.h>
#include <cuda_bf16.h>
#include <math.h>
#include <stdint.h>

#define NN 100000
#define EE 1600000
#define HH 128
#define BN_EPS 1e-5f
#define CHUNK 512
#define NCHUNK ((NN + CHUNK - 1) / CHUNK)   // 196

// ---------------- device scratch (no allocations allowed) ----------------
__device__ __align__(16) float g_H[NN * HH];     // current hidden state
__device__ __align__(16) float g_Z[NN * HH];     // pre-BN GEMM output
__device__ __align__(16) float g_AGG[NN * HH];   // SpMM output
__device__ __align__(16) int   g_degi[NN];       // in-degree (int)
__device__ __align__(16) int   g_off[NN + 1];    // CSR offsets (by destination)
__device__ __align__(16) int   g_cur[NN];        // scatter cursors
__device__ __align__(16) int   g_src[EE];        // CSR: source node per slot
__device__ __align__(16) float g_ev[EE];         // CSR: normalized edge value
__device__ __align__(16) int   g_csum[NCHUNK];   // chunk sums for scan
__device__ __align__(16) float g_sum[HH];
__device__ __align__(16) float g_sumsq[HH];
// swizzled k-major bf16 weight images (3 weights x 32KB each, hi + lo)
__device__ __align__(16) char g_Whi[3 * 32768];
__device__ __align__(16) char g_Wlo[3 * 32768];

// 256B-row swizzle: XOR 16B-chunk index bits[6:4] with row%8 (bits[10:8])
#define SWZ(b) ((b) ^ ((((b) >> 8) & 7u) << 4))

// smem layout for tc gemm (bytes)
#define GS_AHI   0
#define GS_ALO   32768
#define GS_BHI   65536
#define GS_BLO   98304
#define GS_STAT  131072          // 128 sums + 128 ssq (floats)
#define GS_TOTAL (131072 + 1024)

// ---------------- ptx helpers ----------------
__device__ __forceinline__ uint32_t smem_u32(const void* p) {
    uint32_t a;
    asm("{ .reg .u64 t; cvta.to.shared.u64 t, %1; cvt.u32.u64 %0, t; }" : "=r"(a) : "l"(p));
    return a;
}
__device__ __forceinline__ void ldsm_x4(uint32_t* r, uint32_t addr) {
    asm volatile("ldmatrix.sync.aligned.m8n8.x4.shared.b16 {%0,%1,%2,%3}, [%4];"
                 : "=r"(r[0]), "=r"(r[1]), "=r"(r[2]), "=r"(r[3]) : "r"(addr));
}
__device__ __forceinline__ void ldsm_x4_t(uint32_t* r, uint32_t addr) {
    asm volatile("ldmatrix.sync.aligned.m8n8.x4.trans.shared.b16 {%0,%1,%2,%3}, [%4];"
                 : "=r"(r[0]), "=r"(r[1]), "=r"(r[2]), "=r"(r[3]) : "r"(addr));
}
__device__ __forceinline__ void mma16816(float* d, const uint32_t* a, const uint32_t* b) {
    asm volatile("mma.sync.aligned.m16n8k16.row.col.f32.bf16.bf16.f32 "
                 "{%0,%1,%2,%3}, {%4,%5,%6,%7}, {%8,%9}, {%0,%1,%2,%3};"
                 : "+f"(d[0]), "+f"(d[1]), "+f"(d[2]), "+f"(d[3])
                 : "r"(a[0]), "r"(a[1]), "r"(a[2]), "r"(a[3]), "r"(b[0]), "r"(b[1]));
}

// ---------------- utility kernels ----------------
__global__ void zero_int(int* p, int n) {
    int i = blockIdx.x * blockDim.x + threadIdx.x;
    int stride = gridDim.x * blockDim.x;
    for (; i < n; i += stride) p[i] = 0;
}

__global__ void zero_stats_kernel() {
    int i = threadIdx.x;
    if (i < HH) { g_sum[i] = 0.f; g_sumsq[i] = 0.f; }
}

__global__ void degree_kernel(const int* __restrict__ col) {
    int e = blockIdx.x * blockDim.x + threadIdx.x;
    if (e < EE) atomicAdd(&g_degi[col[e]], 1);
}

// ---------------- CSR build: two-level exclusive scan ----------------
__global__ void chunk_sums_kernel() {
    __shared__ int sh[CHUNK];
    int t = threadIdx.x;
    int n = blockIdx.x * CHUNK + t;
    sh[t] = (n < NN) ? g_degi[n] : 0;
    __syncthreads();
    for (int s = CHUNK / 2; s > 0; s >>= 1) {
        if (t < s) sh[t] += sh[t + s];
        __syncthreads();
    }
    if (t == 0) g_csum[blockIdx.x] = sh[0];
}

__global__ void scan_csum_kernel() {   // 1 block, 256 threads, exclusive scan of NCHUNK
    __shared__ int sh[256];
    int t = threadIdx.x;
    int v = (t < NCHUNK) ? g_csum[t] : 0;
    sh[t] = v;
    __syncthreads();
    for (int s = 1; s < 256; s <<= 1) {
        int a = (t >= s) ? sh[t - s] : 0;
        __syncthreads();
        sh[t] += a;
        __syncthreads();
    }
    if (t < NCHUNK) g_csum[t] = sh[t] - v;
}

__global__ void scan_offsets_kernel() {
    __shared__ int sh[CHUNK];
    int t = threadIdx.x;
    int n = blockIdx.x * CHUNK + t;
    int v = (n < NN) ? g_degi[n] : 0;
    sh[t] = v;
    __syncthreads();
    for (int s = 1; s < CHUNK; s <<= 1) {
        int add = (t >= s) ? sh[t - s] : 0;
        __syncthreads();
        sh[t] += add;
        __syncthreads();
    }
    int excl = sh[t] - v + g_csum[blockIdx.x];
    if (n < NN) { g_off[n] = excl; g_cur[n] = excl; }
    if (n == NN - 1) g_off[NN] = excl + v;   // == EE
}

__global__ void val_scatter_kernel(const int* __restrict__ row, const int* __restrict__ col,
                                   const float* __restrict__ w) {
    int e = blockIdx.x * blockDim.x + threadIdx.x;
    if (e < EE) {
        int r = row[e], c = col[e];
        float v = w[e] * rsqrtf((float)g_degi[c]) * rsqrtf((float)g_degi[r]);
        if (!isfinite(v)) v = 0.f;   // nan_to_num
        int p = atomicAdd(&g_cur[c], 1);
        g_src[p] = r;
        g_ev[p]  = v;
    }
}

// ---------------- weight conversion: W[k][n] fp32 -> hi/lo bf16 swizzled k-major image ----------------
__global__ void wconvert_kernel(const float* __restrict__ fc_w, const float* __restrict__ conv_w) {
    int idx = blockIdx.x * blockDim.x + threadIdx.x;
    if (idx >= 3 * 16384) return;
    int w   = idx >> 14;
    int rem = idx & 16383;
    int k = rem >> 7;      // input index (row)
    int n = rem & 127;     // output index (col)
    float v = (w == 0) ? fc_w[rem] : conv_w[(w - 1) * 16384 + rem];
    __nv_bfloat16 hi = __float2bfloat16_rn(v);
    __nv_bfloat16 lo = __float2bfloat16_rn(v - __bfloat162float(hi));
    uint32_t byte = (uint32_t)k * 256u + (uint32_t)n * 2u;
    uint32_t sw = SWZ(byte);
    *(__nv_bfloat16*)(g_Whi + (size_t)w * 32768 + sw) = hi;
    *(__nv_bfloat16*)(g_Wlo + (size_t)w * 32768 + sw) = lo;
}

// ---------------- SpMM (CSR by destination): one warp per node ----------------
__global__ __launch_bounds__(256) void spmm_csr_kernel() {
    int warp = (blockIdx.x * blockDim.x + threadIdx.x) >> 5;
    int lane = threadIdx.x & 31;
    if (warp >= NN) return;
    int s = g_off[warp];
    int e = g_off[warp + 1];
    const float4* H4 = reinterpret_cast<const float4*>(g_H);
    float4 acc = make_float4(0.f, 0.f, 0.f, 0.f);
    int k = s;
    for (; k + 1 < e; k += 2) {
        int   s0 = g_src[k],   s1 = g_src[k + 1];
        float v0 = g_ev[k],    v1 = g_ev[k + 1];
        float4 a = H4[(size_t)s0 * 32 + lane];
        float4 b = H4[(size_t)s1 * 32 + lane];
        acc.x += v0 * a.x + v1 * b.x;
        acc.y += v0 * a.y + v1 * b.y;
        acc.z += v0 * a.z + v1 * b.z;
        acc.w += v0 * a.w + v1 * b.w;
    }
    if (k < e) {
        int   s0 = g_src[k];
        float v0 = g_ev[k];
        float4 a = H4[(size_t)s0 * 32 + lane];
        acc.x += v0 * a.x; acc.y += v0 * a.y;
        acc.z += v0 * a.z; acc.w += v0 * a.w;
    }
    reinterpret_cast<float4*>(g_AGG)[(size_t)warp * 32 + lane] = acc;
}

// ---------------- mma.sync GEMM: C[M,128] = A[M,128] @ W + bias (3xBF16, fp32 acc) ----------------
// Fused BN-stats epilogue into g_sum/g_sumsq.
__global__ __launch_bounds__(256, 1) void gemm_mma_kernel(
    const float* __restrict__ A,
    const char* __restrict__ Whi,   // swizzled 32KB image
    const char* __restrict__ Wlo,
    const float* __restrict__ bias,
    float* __restrict__ C, int M)
{
    extern __shared__ __align__(1024) char smem[];
    uint32_t sb = smem_u32(smem);
    const int tid  = threadIdx.x;
    const int wid  = tid >> 5;
    const int lane = tid & 31;
    const int row0 = blockIdx.x * 128;

    float* s_stat = reinterpret_cast<float*>(smem + GS_STAT);
    s_stat[tid] = 0.f;    // 256 floats: [0:128) sums, [128:256) ssq

    // copy weight images into smem (32KB each = 2048 uint4)
    {
        const uint4* wh = reinterpret_cast<const uint4*>(Whi);
        const uint4* wl = reinterpret_cast<const uint4*>(Wlo);
        uint4* sh = reinterpret_cast<uint4*>(smem + GS_BHI);
        uint4* sl = reinterpret_cast<uint4*>(smem + GS_BLO);
        #pragma unroll
        for (int i = 0; i < 8; i++) {
            sh[tid + i * 256] = wh[tid + i * 256];
            sl[tid + i * 256] = wl[tid + i * 256];
        }
    }

    // load A tile (128 x 128 fp32), split hi/lo bf16, store swizzled k-major
    {
        const float4* A4 = reinterpret_cast<const float4*>(A);
        #pragma unroll
        for (int i = 0; i < 16; i++) {
            int idx = tid + i * 256;
            int m  = idx >> 5;        // 0..127
            int kg = idx & 31;        // float4 group
            int gr = row0 + m;
            float4 a = (gr < M) ? A4[(size_t)gr * 32 + kg] : make_float4(0.f, 0.f, 0.f, 0.f);
            __nv_bfloat16 h0 = __float2bfloat16_rn(a.x);
            __nv_bfloat16 h1 = __float2bfloat16_rn(a.y);
            __nv_bfloat16 h2 = __float2bfloat16_rn(a.z);
            __nv_bfloat16 h3 = __float2bfloat16_rn(a.w);
            __nv_bfloat16 l0 = __float2bfloat16_rn(a.x - __bfloat162float(h0));
            __nv_bfloat16 l1 = __float2bfloat16_rn(a.y - __bfloat162float(h1));
            __nv_bfloat16 l2 = __float2bfloat16_rn(a.z - __bfloat162float(h2));
            __nv_bfloat16 l3 = __float2bfloat16_rn(a.w - __bfloat162float(h3));
            uint32_t byte = (uint32_t)m * 256u + (uint32_t)kg * 8u;
            uint32_t sw = SWZ(byte);
            *reinterpret_cast<__nv_bfloat162*>(smem + GS_AHI + sw)     = __halves2bfloat162(h0, h1);
            *reinterpret_cast<__nv_bfloat162*>(smem + GS_AHI + sw + 4) = __halves2bfloat162(h2, h3);
            *reinterpret_cast<__nv_bfloat162*>(smem + GS_ALO + sw)     = __halves2bfloat162(l0, l1);
            *reinterpret_cast<__nv_bfloat162*>(smem + GS_ALO + sw + 4) = __halves2bfloat162(l2, l3);
        }
    }
    __syncthreads();

    // per-lane ldmatrix address components
    const uint32_t a_m  = (uint32_t)(wid * 16) + (lane & 7) + ((lane >> 3) & 1) * 8;
    const uint32_t a_ks = (uint32_t)(lane >> 4) * 8;
    const uint32_t b_ks = (uint32_t)(lane & 7) + ((lane >> 3) & 1) * 8;
    const uint32_t b_ns = (uint32_t)((lane >> 4) & 1) * 8;

    float acc[64];
    #pragma unroll
    for (int i = 0; i < 64; i++) acc[i] = 0.f;

    const uint32_t abase[3] = { sb + GS_AHI, sb + GS_AHI, sb + GS_ALO };
    const uint32_t bbase[3] = { sb + GS_BHI, sb + GS_BLO, sb + GS_BHI };

    #pragma unroll
    for (int p = 0; p < 3; p++) {
        #pragma unroll
        for (int kc = 0; kc < 8; kc++) {
            uint32_t afrag[4];
            uint32_t ab = a_m * 256u + (kc * 16u + a_ks) * 2u;
            ldsm_x4(afrag, abase[p] + SWZ(ab));
            #pragma unroll
            for (int np = 0; np < 8; np++) {
                uint32_t bfrag[4];
                uint32_t bb = (kc * 16u + b_ks) * 256u + (np * 16u + b_ns) * 2u;
                ldsm_x4_t(bfrag, bbase[p] + SWZ(bb));
                mma16816(&acc[(2 * np) * 4],     afrag, &bfrag[0]);
                mma16816(&acc[(2 * np + 1) * 4], afrag, &bfrag[2]);
            }
        }
    }

    // epilogue: bias add, store, fused BN stats
    int r0 = row0 + wid * 16 + (lane >> 2);
    int r1 = r0 + 8;
    bool v0 = r0 < M, v1 = r1 < M;
    int cb = (lane & 3) * 2;

    #pragma unroll
    for (int nt = 0; nt < 16; nt++) {
        int c = nt * 8 + cb;
        float b0 = __ldg(&bias[c]);
        float b1 = __ldg(&bias[c + 1]);
        float o00 = acc[nt * 4 + 0] + b0;
        float o01 = acc[nt * 4 + 1] + b1;
        float o10 = acc[nt * 4 + 2] + b0;
        float o11 = acc[nt * 4 + 3] + b1;
        if (v0) *reinterpret_cast<float2*>(&C[(size_t)r0 * 128 + c]) = make_float2(o00, o01);
        if (v1) *reinterpret_cast<float2*>(&C[(size_t)r1 * 128 + c]) = make_float2(o10, o11);

        float s0 = (v0 ? o00 : 0.f) + (v1 ? o10 : 0.f);
        float s1 = (v0 ? o01 : 0.f) + (v1 ? o11 : 0.f);
        float q0 = (v0 ? o00 * o00 : 0.f) + (v1 ? o10 * o10 : 0.f);
        float q1 = (v0 ? o01 * o01 : 0.f) + (v1 ? o11 * o11 : 0.f);
        #pragma unroll
        for (int m = 4; m <= 16; m <<= 1) {
            s0 += __shfl_xor_sync(0xFFFFFFFFu, s0, m);
            s1 += __shfl_xor_sync(0xFFFFFFFFu, s1, m);
            q0 += __shfl_xor_sync(0xFFFFFFFFu, q0, m);
            q1 += __shfl_xor_sync(0xFFFFFFFFu, q1, m);
        }
        if (lane < 4) {
            atomicAdd(&s_stat[c], s0);
            atomicAdd(&s_stat[c + 1], s1);
            atomicAdd(&s_stat[128 + c], q0);
            atomicAdd(&s_stat[128 + c + 1], q1);
        }
    }
    __syncthreads();
    if (tid < 128) {
        atomicAdd(&g_sum[tid],   s_stat[tid]);
        atomicAdd(&g_sumsq[tid], s_stat[128 + tid]);
    }
}

// ---------------- BN apply + ReLU (+ optional residual) ----------------
__global__ void bn_apply_kernel(const float* __restrict__ z,
                                const float* __restrict__ gamma,
                                const float* __restrict__ beta,
                                const float* __restrict__ res,  // may be null
                                float* __restrict__ out)
{
    const float inv_n = 1.0f / (float)NN;
    int i = blockIdx.x * blockDim.x + threadIdx.x;
    int stride = gridDim.x * blockDim.x;
    const int n4 = NN * (HH / 4);
    for (; i < n4; i += stride) {
        int c0 = (i & 31) * 4;
        float4 zv = reinterpret_cast<const float4*>(z)[i];
        float o[4] = {zv.x, zv.y, zv.z, zv.w};
        #pragma unroll
        for (int j = 0; j < 4; j++) {
            int c = c0 + j;
            float m  = g_sum[c] * inv_n;
            float vr = g_sumsq[c] * inv_n - m * m;
            float rs = rsqrtf(vr + BN_EPS);
            float y = (o[j] - m) * rs * gamma[c] + beta[c];
            o[j] = fmaxf(y, 0.f);
        }
        float4 ov = make_float4(o[0], o[1], o[2], o[3]);
        if (res != nullptr) {
            float4 rv = reinterpret_cast<const float4*>(res)[i];
            ov.x += rv.x; ov.y += rv.y; ov.z += rv.z; ov.w += rv.w;
        }
        reinterpret_cast<float4*>(out)[i] = ov;
    }
}

// ---------------- launch ----------------
extern "C" void kernel_launch(void* const* d_in, const int* in_sizes, int n_in,
                              void* d_out, int out_size)
{
    const float* x      = (const float*)d_in[0];
    const int*   ei     = (const int*)  d_in[1];
    const float* ew     = (const float*)d_in[2];
    const float* fc_w   = (const float*)d_in[3];
    const float* fc_b   = (const float*)d_in[4];
    const float* conv_w = (const float*)d_in[5];
    const float* conv_b = (const float*)d_in[6];
    const float* gamma  = (const float*)d_in[7];
    const float* beta   = (const float*)d_in[8];
    float* out = (float*)d_out;

    const int* row = ei;
    const int* col = ei + EE;

    void *pH, *pZ, *pAGG, *pDegi, *pWhi, *pWlo;
    cudaGetSymbolAddress(&pH, g_H);
    cudaGetSymbolAddress(&pZ, g_Z);
    cudaGetSymbolAddress(&pAGG, g_AGG);
    cudaGetSymbolAddress(&pDegi, g_degi);
    cudaGetSymbolAddress(&pWhi, g_Whi);
    cudaGetSymbolAddress(&pWlo, g_Wlo);
    float* H   = (float*)pH;
    float* Z   = (float*)pZ;
    float* AGG = (float*)pAGG;
    const char* Whi = (const char*)pWhi;
    const char* Wlo = (const char*)pWlo;

    static int smem_set = 0;
    if (!smem_set) {
        cudaFuncSetAttribute(gemm_mma_kernel, cudaFuncAttributeMaxDynamicSharedMemorySize, GS_TOTAL);
        smem_set = 1;
    }

    const int egrid = (EE + 255) / 256;
    const int ggrid = (NN + 127) / 128;   // 782

    // ---- CSR build ----
    zero_int<<<128, 256>>>((int*)pDegi, NN);
    degree_kernel<<<egrid, 256>>>(col);
    chunk_sums_kernel<<<NCHUNK, CHUNK>>>();
    scan_csum_kernel<<<1, 256>>>();
    scan_offsets_kernel<<<NCHUNK, CHUNK>>>();
    val_scatter_kernel<<<egrid, 256>>>(row, col, ew);

    // ---- weight conversion ----
    wconvert_kernel<<<(3 * 16384 + 255) / 256, 256>>>(fc_w, conv_w);

    // ---- input projection + BN + ReLU ----
    zero_stats_kernel<<<1, 128>>>();
    gemm_mma_kernel<<<ggrid, 256, GS_TOTAL>>>(x, Whi, Wlo, fc_b, Z, NN);
    bn_apply_kernel<<<4096, 256>>>(Z, gamma, beta, nullptr, H);

    for (int l = 0; l < 2; l++) {
        spmm_csr_kernel<<<(NN * 32 + 255) / 256, 256>>>();
        zero_stats_kernel<<<1, 128>>>();
        gemm_mma_kernel<<<ggrid, 256, GS_TOTAL>>>(AGG, Whi + (size_t)(l + 1) * 32768,
                                                  Wlo + (size_t)(l + 1) * 32768,
                                                  conv_b + l * HH, Z, NN);
        bn_apply_kernel<<<4096, 256>>>(Z, gamma + (l + 1) * HH, beta + (l + 1) * HH,
                                       H, (l == 1) ? out : H);
    }
}